// round 2
// baseline (speedup 1.0000x reference)
#include <cuda_runtime.h>

// MoE router: logits = x @ W^T, softmax, top-2 (+renorm), full probs.
// Output layout (fp32): [0,2T) top2 probs | [2T,4T) top2 indices (as float) | [4T,68T) probs.

#define TM 64          // tokens per CTA
#define KC 64          // K-chunk
#define NE 64          // experts (E)
#define XS_STRIDE 65   // odd stride -> conflict-free broadcast x reads
#define WS_STRIDE 68   // 16B-aligned rows for LDS.128 expert reads

__device__ __forceinline__ unsigned long long pack2(float v) {
    unsigned long long r;
    asm("mov.b64 %0, {%1, %2};" : "=l"(r) : "f"(v), "f"(v));
    return r;
}
__device__ __forceinline__ void ffma2(unsigned long long& d,
                                      unsigned long long a, unsigned long long b) {
    asm("fma.rn.f32x2 %0, %1, %2, %0;" : "+l"(d) : "l"(a), "l"(b));
}
__device__ __forceinline__ float2 unpack2(unsigned long long v) {
    float2 f;
    asm("mov.b64 {%0, %1}, %2;" : "=f"(f.x), "=f"(f.y) : "l"(v));
    return f;
}

__global__ __launch_bounds__(64)
void gemm_logits_kernel(const float* __restrict__ x,
                        const float* __restrict__ w,
                        float* __restrict__ logits, int D) {
    __shared__ __align__(16) float xs[TM * XS_STRIDE];
    __shared__ __align__(16) float ws[KC * WS_STRIDE];

    const int tid = threadIdx.x;
    const long long tBase = (long long)blockIdx.x * TM;
    const int tx = tid & 7;   // experts 8*tx .. 8*tx+7
    const int ty = tid >> 3;  // tokens ty*8 .. ty*8+7

    unsigned long long acc[8][4];
#pragma unroll
    for (int i = 0; i < 8; i++)
#pragma unroll
        for (int p = 0; p < 4; p++) acc[i][p] = 0ULL;

    const int dd4 = tid & 15;
    const int r0 = tid >> 4;
    const float* xg = x + tBase * D;

    for (int d0 = 0; d0 < D; d0 += KC) {
        // fill x tile [token][kk], natural layout, stride 65
#pragma unroll
        for (int i = 0; i < 16; i++) {
            int r = r0 + 4 * i;
            float4 v = *(const float4*)(xg + (long long)r * D + d0 + 4 * dd4);
            float* dst = &xs[r * XS_STRIDE + 4 * dd4];
            dst[0] = v.x; dst[1] = v.y; dst[2] = v.z; dst[3] = v.w;
        }
        // fill w tile transposed [kk][expert]; expert = tid (64 threads = 64 experts)
        const float* wg = w + (long long)tid * D + d0;
#pragma unroll
        for (int i = 0; i < 16; i++) {
            float4 v = *(const float4*)(wg + 4 * i);
            ws[(4 * i + 0) * WS_STRIDE + tid] = v.x;
            ws[(4 * i + 1) * WS_STRIDE + tid] = v.y;
            ws[(4 * i + 2) * WS_STRIDE + tid] = v.z;
            ws[(4 * i + 3) * WS_STRIDE + tid] = v.w;
        }
        __syncthreads();

#pragma unroll 4
        for (int kk = 0; kk < KC; kk++) {
            const float* wrow = &ws[kk * WS_STRIDE + 8 * tx];
            ulonglong2 w01 = *(const ulonglong2*)(wrow);
            ulonglong2 w23 = *(const ulonglong2*)(wrow + 4);
#pragma unroll
            for (int i = 0; i < 8; i++) {
                unsigned long long xp = pack2(xs[(ty * 8 + i) * XS_STRIDE + kk]);
                ffma2(acc[i][0], xp, w01.x);
                ffma2(acc[i][1], xp, w01.y);
                ffma2(acc[i][2], xp, w23.x);
                ffma2(acc[i][3], xp, w23.y);
            }
        }
        __syncthreads();
    }

    // epilogue: write logits [T, 64]
#pragma unroll
    for (int i = 0; i < 8; i++) {
        long long t = tBase + ty * 8 + i;
        float* o = logits + t * NE + 8 * tx;
        float2 a = unpack2(acc[i][0]), b = unpack2(acc[i][1]);
        float2 c = unpack2(acc[i][2]), d2 = unpack2(acc[i][3]);
        float4 v0 = make_float4(a.x, a.y, b.x, b.y);
        float4 v1 = make_float4(c.x, c.y, d2.x, d2.y);
        *(float4*)(o) = v0;
        *(float4*)(o + 4) = v1;
    }
}

// one warp per token: softmax over 64, top-2 with index tiebreak, renorm
__global__ void softmax_topk_kernel(const float* __restrict__ logits,
                                    float* __restrict__ out_p,
                                    float* __restrict__ out_i,
                                    float* __restrict__ probs,
                                    long long T) {
    const int lane = threadIdx.x & 31;
    const long long t = (long long)blockIdx.x * (blockDim.x >> 5) + (threadIdx.x >> 5);
    if (t >= T) return;

    float2 l = *(const float2*)(logits + t * 64 + 2 * lane);

    float m = fmaxf(l.x, l.y);
#pragma unroll
    for (int o = 16; o; o >>= 1) m = fmaxf(m, __shfl_xor_sync(0xffffffffu, m, o));

    float e0 = __expf(l.x - m), e1 = __expf(l.y - m);
    float s = e0 + e1;
#pragma unroll
    for (int o = 16; o; o >>= 1) s += __shfl_xor_sync(0xffffffffu, s, o);
    float inv = 1.0f / s;
    float p0 = e0 * inv, p1 = e1 * inv;

    *(float2*)(probs + t * 64 + 2 * lane) = make_float2(p0, p1);

    // local sorted pair (tie -> lower index first, matching jax.lax.top_k)
    float a1, a2; int i1, i2;
    if (p0 >= p1) { a1 = p0; i1 = 2 * lane;     a2 = p1; i2 = 2 * lane + 1; }
    else          { a1 = p1; i1 = 2 * lane + 1; a2 = p0; i2 = 2 * lane; }

#pragma unroll
    for (int o = 16; o; o >>= 1) {
        float b1 = __shfl_xor_sync(0xffffffffu, a1, o);
        int   j1 = __shfl_xor_sync(0xffffffffu, i1, o);
        float b2 = __shfl_xor_sync(0xffffffffu, a2, o);
        int   j2 = __shfl_xor_sync(0xffffffffu, i2, o);
        bool b1_wins = (b1 > a1) || (b1 == a1 && j1 < i1);
        if (b1_wins) {
            bool a1_second = (a1 > b2) || (a1 == b2 && i1 < j2);
            float na2 = a1_second ? a1 : b2;
            int   ni2 = a1_second ? i1 : j2;
            a1 = b1; i1 = j1; a2 = na2; i2 = ni2;
        } else {
            bool b1_second = (b1 > a2) || (b1 == a2 && j1 < i2);
            if (b1_second) { a2 = b1; i2 = j1; }
        }
    }

    if (lane == 0) {
        float sn = a1 + a2;
        out_p[t * 2 + 0] = a1 / sn;
        out_p[t * 2 + 1] = a2 / sn;
        out_i[t * 2 + 0] = (float)i1;
        out_i[t * 2 + 1] = (float)i2;
    }
}

extern "C" void kernel_launch(void* const* d_in, const int* in_sizes, int n_in,
                              void* d_out, int out_size) {
    const float* x = (const float*)d_in[0];
    const float* w = (const float*)d_in[1];
    float* out = (float*)d_out;

    // out = [T,2] probs + [T,2] idx + [T,64] probs  => 68 floats per token
    long long T = (long long)out_size / 68;
    int D = (int)((long long)in_sizes[0] / T);

    float* out_p = out;            // [T,2]
    float* out_i = out + 2 * T;    // [T,2] indices as float
    float* probs = out + 4 * T;    // [T,64], used as logits scratch first

    gemm_logits_kernel<<<(int)(T / TM), 64>>>(x, w, probs, D);
    softmax_topk_kernel<<<(int)((T + 7) / 8), 256>>>(probs, out_p, out_i, probs, T);
}

// round 4
// speedup vs baseline: 1.6875x; 1.6875x over previous
#include <cuda_runtime.h>

// MoE router: logits = x @ W^T, softmax over E=64, top-2 (+renorm), full probs.
// Output (fp32): [0,2T) top2 probs | [2T,4T) top2 indices (as float) | [4T,68T) probs.

#define TM 128         // tokens per CTA
#define KC 32          // K-chunk
#define NE 64          // experts
#define XS_S 132       // xs row stride (words): [kk][token], 16B-aligned, read-conflict-free
#define WS_S 68        // ws row stride (words): [kk][expert], 16B-aligned

__device__ __forceinline__ unsigned long long pack2(float v) {
    unsigned long long r;
    asm("mov.b64 %0, {%1, %2};" : "=l"(r) : "f"(v), "f"(v));
    return r;
}
__device__ __forceinline__ void ffma2(unsigned long long& d,
                                      unsigned long long a, unsigned long long b) {
    asm("fma.rn.f32x2 %0, %1, %2, %0;" : "+l"(d) : "l"(a), "l"(b));
}
__device__ __forceinline__ float2 unpack2(unsigned long long v) {
    float2 f;
    asm("mov.b64 {%0, %1}, %2;" : "=f"(f.x), "=f"(f.y) : "l"(v));
    return f;
}

__global__ __launch_bounds__(256, 1)
void gemm_logits_kernel(const float* __restrict__ x,
                        const float* __restrict__ w,
                        float* __restrict__ logits, int D) {
    __shared__ __align__(16) float xs[KC][XS_S];  // [kk][token]
    __shared__ __align__(16) float ws[KC][WS_S];  // [kk][expert]

    const int tid = threadIdx.x;
    const long long tBase = (long long)blockIdx.x * TM;
    const int tx = tid & 15;   // experts 4*tx .. 4*tx+3
    const int ty = tid >> 4;   // tokens ty*8 .. ty*8+7

    // fill-role indices: 8 threads per row, c4 = 16B column
    const int frow = tid >> 3;        // 0..31
    const int c4   = tid & 7;         // 0..7  -> smem rows 4*c4 .. 4*c4+3

    const float* xg = x + tBase * D + (long long)frow * D + 4 * c4;
    const float* wg = w + (long long)frow * D + 4 * c4;

    unsigned long long acc[8][2];
#pragma unroll
    for (int i = 0; i < 8; i++) { acc[i][0] = 0ULL; acc[i][1] = 0ULL; }

    float4 sx[4], sw[2];

    // prologue: stage chunk 0
#pragma unroll
    for (int j = 0; j < 4; j++) sx[j] = *(const float4*)(xg + (long long)(32 * j) * D);
#pragma unroll
    for (int j = 0; j < 2; j++) sw[j] = *(const float4*)(wg + (long long)(32 * j) * D);

    for (int d0 = 0; d0 < D; d0 += KC) {
        // store staged regs -> smem (transposed: row = k within chunk)
#pragma unroll
        for (int j = 0; j < 4; j++) {
            int tok = frow + 32 * j;
            xs[4 * c4 + 0][tok] = sx[j].x;
            xs[4 * c4 + 1][tok] = sx[j].y;
            xs[4 * c4 + 2][tok] = sx[j].z;
            xs[4 * c4 + 3][tok] = sx[j].w;
        }
#pragma unroll
        for (int j = 0; j < 2; j++) {
            int e = frow + 32 * j;
            ws[4 * c4 + 0][e] = sw[j].x;
            ws[4 * c4 + 1][e] = sw[j].y;
            ws[4 * c4 + 2][e] = sw[j].z;
            ws[4 * c4 + 3][e] = sw[j].w;
        }
        __syncthreads();

        // stage next chunk while computing this one
        if (d0 + KC < D) {
            const float* xn = xg + d0 + KC;
            const float* wn = wg + d0 + KC;
#pragma unroll
            for (int j = 0; j < 4; j++) sx[j] = *(const float4*)(xn + (long long)(32 * j) * D);
#pragma unroll
            for (int j = 0; j < 2; j++) sw[j] = *(const float4*)(wn + (long long)(32 * j) * D);
        }

#pragma unroll 8
        for (int kk = 0; kk < KC; kk++) {
            float4 xa = *(const float4*)&xs[kk][ty * 8];
            float4 xb = *(const float4*)&xs[kk][ty * 8 + 4];
            ulonglong2 wv = *(const ulonglong2*)&ws[kk][tx * 4];
            {
                unsigned long long xp;
                xp = pack2(xa.x); ffma2(acc[0][0], xp, wv.x); ffma2(acc[0][1], xp, wv.y);
                xp = pack2(xa.y); ffma2(acc[1][0], xp, wv.x); ffma2(acc[1][1], xp, wv.y);
                xp = pack2(xa.z); ffma2(acc[2][0], xp, wv.x); ffma2(acc[2][1], xp, wv.y);
                xp = pack2(xa.w); ffma2(acc[3][0], xp, wv.x); ffma2(acc[3][1], xp, wv.y);
                xp = pack2(xb.x); ffma2(acc[4][0], xp, wv.x); ffma2(acc[4][1], xp, wv.y);
                xp = pack2(xb.y); ffma2(acc[5][0], xp, wv.x); ffma2(acc[5][1], xp, wv.y);
                xp = pack2(xb.z); ffma2(acc[6][0], xp, wv.x); ffma2(acc[6][1], xp, wv.y);
                xp = pack2(xb.w); ffma2(acc[7][0], xp, wv.x); ffma2(acc[7][1], xp, wv.y);
            }
        }
        __syncthreads();
    }

    // epilogue: write logits [T, 64]
#pragma unroll
    for (int i = 0; i < 8; i++) {
        long long t = tBase + ty * 8 + i;
        float2 a = unpack2(acc[i][0]), b = unpack2(acc[i][1]);
        *(float4*)(logits + t * NE + 4 * tx) = make_float4(a.x, a.y, b.x, b.y);
    }
}

// one warp per token: softmax over 64, top-2 with index tiebreak, renorm
__global__ void softmax_topk_kernel(const float* __restrict__ logits,
                                    float* __restrict__ out_p,
                                    float* __restrict__ out_i,
                                    float* __restrict__ probs,
                                    long long T) {
    const int lane = threadIdx.x & 31;
    const long long t = (long long)blockIdx.x * (blockDim.x >> 5) + (threadIdx.x >> 5);
    if (t >= T) return;

    float2 l = *(const float2*)(logits + t * 64 + 2 * lane);

    float m = fmaxf(l.x, l.y);
#pragma unroll
    for (int o = 16; o; o >>= 1) m = fmaxf(m, __shfl_xor_sync(0xffffffffu, m, o));

    float e0 = __expf(l.x - m), e1 = __expf(l.y - m);
    float s = e0 + e1;
#pragma unroll
    for (int o = 16; o; o >>= 1) s += __shfl_xor_sync(0xffffffffu, s, o);
    float inv = 1.0f / s;
    float p0 = e0 * inv, p1 = e1 * inv;

    *(float2*)(probs + t * 64 + 2 * lane) = make_float2(p0, p1);

    float a1, a2; int i1, i2;
    if (p0 >= p1) { a1 = p0; i1 = 2 * lane;     a2 = p1; i2 = 2 * lane + 1; }
    else          { a1 = p1; i1 = 2 * lane + 1; a2 = p0; i2 = 2 * lane; }

#pragma unroll
    for (int o = 16; o; o >>= 1) {
        float b1 = __shfl_xor_sync(0xffffffffu, a1, o);
        int   j1 = __shfl_xor_sync(0xffffffffu, i1, o);
        float b2 = __shfl_xor_sync(0xffffffffu, a2, o);
        int   j2 = __shfl_xor_sync(0xffffffffu, i2, o);
        bool b1_wins = (b1 > a1) || (b1 == a1 && j1 < i1);
        if (b1_wins) {
            bool a1_second = (a1 > b2) || (a1 == b2 && i1 < j2);
            float na2 = a1_second ? a1 : b2;
            int   ni2 = a1_second ? i1 : j2;
            a1 = b1; i1 = j1; a2 = na2; i2 = ni2;
        } else {
            bool b1_second = (b1 > a2) || (b1 == a2 && j1 < i2);
            if (b1_second) { a2 = b1; i2 = j1; }
        }
    }

    if (lane == 0) {
        float sn = a1 + a2;
        out_p[t * 2 + 0] = a1 / sn;
        out_p[t * 2 + 1] = a2 / sn;
        out_i[t * 2 + 0] = (float)i1;
        out_i[t * 2 + 1] = (float)i2;
    }
}

extern "C" void kernel_launch(void* const* d_in, const int* in_sizes, int n_in,
                              void* d_out, int out_size) {
    const float* x = (const float*)d_in[0];
    const float* w = (const float*)d_in[1];
    float* out = (float*)d_out;

    long long T = (long long)out_size / 68;
    int D = (int)((long long)in_sizes[0] / T);

    float* out_p = out;            // [T,2]
    float* out_i = out + 2 * T;    // [T,2]
    float* probs = out + 4 * T;    // [T,64] (logits scratch, then probs)

    gemm_logits_kernel<<<(int)(T / TM), 256>>>(x, w, probs, D);
    softmax_topk_kernel<<<(int)((T + 7) / 8), 256>>>(probs, out_p, out_i, probs, T);
}

// round 10
// speedup vs baseline: 2.1112x; 1.2511x over previous
#include <cuda_runtime.h>
#include <cstdint>

// MoE router: logits = x @ W^T via mma.sync tf32 3-term compensated split (3xTF32),
// fused softmax + top-2 epilogue. One kernel.
// Output (fp32): [0,2T) top2 probs | [2T,4T) top2 indices | [4T,68T) probs.

#define TM 128          // tokens per CTA
#define KC 32           // K per chunk
#define NE 64           // experts
#define XS_S 36         // smem row stride (words) for x/w tiles -> conflict-free frags
#define LG_S 68         // logits row stride (words), 16B-aligned

#define SMEM_BYTES (TM * LG_S * 4)   // 34816 B >= tile region (6912 floats)

__device__ __forceinline__ uint32_t tf32_hi(float v) {
    uint32_t h;
    asm("cvt.rna.tf32.f32 %0, %1;" : "=r"(h) : "f"(v));
    return h;
}

__device__ __forceinline__ void mma_tf32(float* d, const uint32_t* a, const uint32_t* b) {
    asm volatile(
        "mma.sync.aligned.m16n8k8.row.col.f32.tf32.tf32.f32 "
        "{%0,%1,%2,%3}, {%4,%5,%6,%7}, {%8,%9}, {%0,%1,%2,%3};"
        : "+f"(d[0]), "+f"(d[1]), "+f"(d[2]), "+f"(d[3])
        : "r"(a[0]), "r"(a[1]), "r"(a[2]), "r"(a[3]), "r"(b[0]), "r"(b[1]));
}

__global__ __launch_bounds__(256, 1)
void moe_router_kernel(const float* __restrict__ x,
                       const float* __restrict__ w,
                       float* __restrict__ out_p,
                       float* __restrict__ out_i,
                       float* __restrict__ probs,
                       int D) {
    extern __shared__ __align__(16) float sm[];
    float* xs = sm;                 // [128][36]
    float* ws = sm + TM * XS_S;     // [64][36]

    const int tid = threadIdx.x;
    const int wid = tid >> 5, lane = tid & 31;
    const int g = lane >> 2, tg = lane & 3;
    const int wm = wid & 3;         // M group: tokens wm*32..+31
    const int wn = wid >> 2;        // N group: experts wn*32..+31
    const long long tBase = (long long)blockIdx.x * TM;

    // fill roles
    const int r8 = tid >> 3, c16 = tid & 7;
    const float* xg = x + (tBase + r8) * (long long)D + 4 * c16;
    const float* wg = w + (long long)r8 * D + 4 * c16;

    float acc[2][4][4];
#pragma unroll
    for (int mt = 0; mt < 2; mt++)
#pragma unroll
        for (int nt = 0; nt < 4; nt++)
#pragma unroll
            for (int q = 0; q < 4; q++) acc[mt][nt][q] = 0.f;

    float4 rx[4], rw[2];
#pragma unroll
    for (int j = 0; j < 4; j++) rx[j] = *(const float4*)(xg + (long long)(32 * j) * D);
#pragma unroll
    for (int j = 0; j < 2; j++) rw[j] = *(const float4*)(wg + (long long)(32 * j) * D);

    const int nCh = D / KC;
    for (int i = 0; i < nCh; i++) {
        // store staged regs -> smem [row][k], stride 36
#pragma unroll
        for (int j = 0; j < 4; j++)
            *(float4*)&xs[(r8 + 32 * j) * XS_S + 4 * c16] = rx[j];
#pragma unroll
        for (int j = 0; j < 2; j++)
            *(float4*)&ws[(r8 + 32 * j) * XS_S + 4 * c16] = rw[j];
        __syncthreads();

        if (i + 1 < nCh) {
            const float* xn = xg + (i + 1) * KC;
            const float* wn2 = wg + (i + 1) * KC;
#pragma unroll
            for (int j = 0; j < 4; j++) rx[j] = *(const float4*)(xn + (long long)(32 * j) * D);
#pragma unroll
            for (int j = 0; j < 2; j++) rw[j] = *(const float4*)(wn2 + (long long)(32 * j) * D);
        }

#pragma unroll
        for (int s8 = 0; s8 < 4; s8++) {
            const int kb = 8 * s8;
            uint32_t ah[2][4], al[2][4], bh[4][2], bl[4][2];
#pragma unroll
            for (int mt = 0; mt < 2; mt++) {
                const int t0 = wm * 32 + mt * 16;
                float v0 = xs[(t0 + g) * XS_S + kb + tg];
                float v1 = xs[(t0 + g + 8) * XS_S + kb + tg];
                float v2 = xs[(t0 + g) * XS_S + kb + tg + 4];
                float v3 = xs[(t0 + g + 8) * XS_S + kb + tg + 4];
                ah[mt][0] = tf32_hi(v0); al[mt][0] = __float_as_uint(v0 - __uint_as_float(ah[mt][0]));
                ah[mt][1] = tf32_hi(v1); al[mt][1] = __float_as_uint(v1 - __uint_as_float(ah[mt][1]));
                ah[mt][2] = tf32_hi(v2); al[mt][2] = __float_as_uint(v2 - __uint_as_float(ah[mt][2]));
                ah[mt][3] = tf32_hi(v3); al[mt][3] = __float_as_uint(v3 - __uint_as_float(ah[mt][3]));
            }
#pragma unroll
            for (int nt = 0; nt < 4; nt++) {
                const int e0 = wn * 32 + nt * 8 + g;
                float u0 = ws[e0 * XS_S + kb + tg];
                float u1 = ws[e0 * XS_S + kb + tg + 4];
                bh[nt][0] = tf32_hi(u0); bl[nt][0] = __float_as_uint(u0 - __uint_as_float(bh[nt][0]));
                bh[nt][1] = tf32_hi(u1); bl[nt][1] = __float_as_uint(u1 - __uint_as_float(bh[nt][1]));
            }
#pragma unroll
            for (int mt = 0; mt < 2; mt++)
#pragma unroll
                for (int nt = 0; nt < 4; nt++) {
                    mma_tf32(acc[mt][nt], al[mt], bh[nt]);
                    mma_tf32(acc[mt][nt], ah[mt], bl[nt]);
                    mma_tf32(acc[mt][nt], ah[mt], bh[nt]);
                }
        }
        __syncthreads();
    }

    // ---- epilogue: accums -> smem logits [128][68] ----
    float* lg = sm;
#pragma unroll
    for (int mt = 0; mt < 2; mt++)
#pragma unroll
        for (int nt = 0; nt < 4; nt++) {
            const int row = wm * 32 + mt * 16 + g;
            const int col = wn * 32 + nt * 8 + 2 * tg;
            *(float2*)&lg[row * LG_S + col] = make_float2(acc[mt][nt][0], acc[mt][nt][1]);
            *(float2*)&lg[(row + 8) * LG_S + col] = make_float2(acc[mt][nt][2], acc[mt][nt][3]);
        }
    __syncthreads();

    // warps 0-3: one token per lane; softmax + top-2 in registers
    if (wid < 4) {
        const int tl = wid * 32 + lane;
        float* row = &lg[tl * LG_S];
        float e[64];
#pragma unroll
        for (int c = 0; c < 64; c += 4) {
            float4 v = *(const float4*)(row + c);
            e[c] = v.x; e[c + 1] = v.y; e[c + 2] = v.z; e[c + 3] = v.w;
        }
        float m = e[0];
#pragma unroll
        for (int c = 1; c < 64; c++) m = fmaxf(m, e[c]);
        float sum = 0.f;
#pragma unroll
        for (int c = 0; c < 64; c++) { e[c] = __expf(e[c] - m); sum += e[c]; }
        float a1 = -1.f, a2 = -1.f;
        int i1 = 0, i2 = 0;
#pragma unroll
        for (int c = 0; c < 64; c++) {
            float p = e[c];
            if (p > a1)      { a2 = a1; i2 = i1; a1 = p; i1 = c; }
            else if (p > a2) { a2 = p; i2 = c; }
        }
        const float inv = 1.0f / sum;
#pragma unroll
        for (int c = 0; c < 64; c += 4)
            *(float4*)(row + c) = make_float4(e[c] * inv, e[c + 1] * inv,
                                              e[c + 2] * inv, e[c + 3] * inv);
        const long long t = tBase + tl;
        const float sn = a1 + a2;
        *(float2*)(out_p + t * 2) = make_float2(a1 / sn, a2 / sn);
        *(float2*)(out_i + t * 2) = make_float2((float)i1, (float)i2);
    }
    __syncthreads();

    // coalesced probs writeback: 2048 float4
    {
        float* pg = probs + tBase * 64;
#pragma unroll
        for (int j = 0; j < 8; j++) {
            const int fidx = tid + 256 * j;
            const int trow = fidx >> 4, cc = fidx & 15;
            *(float4*)(pg + (long long)fidx * 4) = *(const float4*)&lg[trow * LG_S + cc * 4];
        }
    }
}

extern "C" void kernel_launch(void* const* d_in, const int* in_sizes, int n_in,
                              void* d_out, int out_size) {
    const float* x = (const float*)d_in[0];
    const float* w = (const float*)d_in[1];
    float* out = (float*)d_out;

    const long long T = (long long)out_size / 68;
    const int D = (int)((long long)in_sizes[0] / T);

    float* out_p = out;           // [T,2]
    float* out_i = out + 2 * T;   // [T,2]
    float* probs = out + 4 * T;   // [T,64]

    moe_router_kernel<<<(int)(T / TM), 256, SMEM_BYTES>>>(x, w, out_p, out_i, probs, D);
}